// round 2
// baseline (speedup 1.0000x reference)
#include <cuda_runtime.h>

typedef unsigned long long u64;

#define WIDTH    1024
#define HALF     512
#define BATCH    8192
#define DEPTH    20
#define TB       16          // batch columns per block
#define NTHREADS 256         // 32 row-threads x 8 batch-pair threads
#define NBLOCKS  (BATCH / TB)

// Pre-packed coefficients: g_pk[layer*HALF + pair] = { (c,c), (s,s) } as 2x f32x2.
__device__ ulonglong2 g_pk[DEPTH * HALF];

__global__ void sincos_kernel(const float* __restrict__ ang) {
    int i = blockIdx.x * blockDim.x + threadIdx.x;
    if (i < DEPTH * HALF) {
        float s, c;
        sincosf(ang[i], &s, &c);
        u64 cc, ss;
        asm("mov.b64 %0, {%1, %1};" : "=l"(cc) : "f"(c));
        asm("mov.b64 %0, {%1, %1};" : "=l"(ss) : "f"(s));
        g_pk[i] = make_ulonglong2(cc, ss);
    }
}

// ---- packed f32x2 helpers (Blackwell) ----
__device__ __forceinline__ u64 mul2(u64 a, u64 b) {
    u64 d; asm("mul.rn.f32x2 %0, %1, %2;" : "=l"(d) : "l"(a), "l"(b)); return d;
}
__device__ __forceinline__ u64 fma2(u64 a, u64 b, u64 c) {
    u64 d; asm("fma.rn.f32x2 %0, %1, %2, %3;" : "=l"(d) : "l"(a), "l"(b), "l"(c)); return d;
}

// Givens rotation on one packed pair of batch columns.
// y0 = c*x0 + s*x1 ; y1 = -s*x0 + c*x1
__device__ __forceinline__ void rot(u64& x0, u64& x1, const ulonglong2 cs) {
    const u64 ns = cs.y ^ 0x8000000080000000ULL;   // (-s,-s), 2x LOP3
    const u64 y0 = fma2(cs.x, x0, mul2(cs.y, x1));
    const u64 y1 = fma2(ns,   x0, mul2(cs.x, x1));
    x0 = y0; x1 = y1;
}

// Swizzled smem index in 8B units. Gives exactly 2 threads per bank-pair
// (optimal: 256B warp access in 2 phases) for BOTH exchange groupings:
//   A: rows rt*32+j (j fixed, rt varies in low 2 bits within a warp)
//   B: rows rt+32*j (j fixed)
__device__ __forceinline__ int sidx(int row, int bp) {
    const int r2  = row ^ ((row >> 6) & 1);
    const int col = bp ^ ((row >> 5) & 3) ^ (((row >> 1) & 1) << 2);
    return r2 * 8 + col;
}

// Five butterfly levels fully in registers. Register j holds:
//   P2==false: row rt*32+j  (coef index = layerbase + rt*16 + m)
//   P2==true : row rt+32*j  (coef index = layerbase + m*32 + rt)
template<bool P2>
__device__ __forceinline__ void pass5(u64* Xv, const ulonglong2* __restrict__ tab, int rt) {
#pragma unroll
    for (int l = 0; l < 5; ++l) {
        const ulonglong2* lt = tab + l * HALF + (P2 ? rt : rt * 16);
        const int sg = 1 << l;
#pragma unroll
        for (int h = 0; h < 2; ++h) {
            ulonglong2 cf[8];
#pragma unroll
            for (int m8 = 0; m8 < 8; ++m8) {
                const int m = h * 8 + m8;
                cf[m8] = __ldg(lt + (P2 ? m * 32 : m));
            }
#pragma unroll
            for (int m8 = 0; m8 < 8; ++m8) {
                const int m = h * 8 + m8;
                const int j = ((m >> l) << (l + 1)) | (m & (sg - 1));
                rot(Xv[j], Xv[j + sg], cf[m8]);
            }
        }
    }
}

extern "C" __global__ void __launch_bounds__(NTHREADS, 2)
butterfly_kernel(const float* __restrict__ X, float* __restrict__ Y)
{
    extern __shared__ u64 tile[];          // 1024 rows x 8 col-pairs x 8B = 64 KB

    const int bp = threadIdx.x & 7;        // which batch-pair (2 columns) of the 16
    const int rt = threadIdx.x >> 3;       // row-thread id, 0..31
    const long long bb = (long long)blockIdx.x * TB + bp * 2;

    u64 Xa[32];                            // 32 rows x 2 batch columns

    // Load, P1 layout: reg j = row rt*32+j. Fully coalesced (4 rows x 64B/warp).
#pragma unroll
    for (int j = 0; j < 32; ++j)
        Xa[j] = *reinterpret_cast<const u64*>(X + (long long)(rt * 32 + j) * BATCH + bb);

    // ---- layers 0-4 (strides 1..16) ----
    pass5<false>(Xa, g_pk + 0 * HALF, rt);

    // exchange P1 -> P2
    __syncthreads();
#pragma unroll
    for (int j = 0; j < 32; ++j) tile[sidx(rt * 32 + j, bp)] = Xa[j];
    __syncthreads();
#pragma unroll
    for (int j = 0; j < 32; ++j) Xa[j] = tile[sidx(rt + 32 * j, bp)];

    // ---- layers 5-9 (strides 32..512) ----
    pass5<true>(Xa, g_pk + 5 * HALF, rt);

    // exchange P2 -> P1
    __syncthreads();
#pragma unroll
    for (int j = 0; j < 32; ++j) tile[sidx(rt + 32 * j, bp)] = Xa[j];
    __syncthreads();
#pragma unroll
    for (int j = 0; j < 32; ++j) Xa[j] = tile[sidx(rt * 32 + j, bp)];

    // ---- layers 10-14 (strides 1..16) ----
    pass5<false>(Xa, g_pk + 10 * HALF, rt);

    // exchange P1 -> P2
    __syncthreads();
#pragma unroll
    for (int j = 0; j < 32; ++j) tile[sidx(rt * 32 + j, bp)] = Xa[j];
    __syncthreads();
#pragma unroll
    for (int j = 0; j < 32; ++j) Xa[j] = tile[sidx(rt + 32 * j, bp)];

    // ---- layers 15-19 (strides 32..512) ----
    pass5<true>(Xa, g_pk + 15 * HALF, rt);

    // Store, P2 layout: reg j = row rt+32j. Coalesced.
#pragma unroll
    for (int j = 0; j < 32; ++j)
        *reinterpret_cast<u64*>(Y + (long long)(rt + 32 * j) * BATCH + bb) = Xa[j];
}

extern "C" void kernel_launch(void* const* d_in, const int* in_sizes, int n_in,
                              void* d_out, int out_size)
{
    const float* X = (const float*)d_in[0];
    const float* A = (const float*)d_in[1];
    if (n_in >= 2 && in_sizes[0] < in_sizes[1]) {   // defensive: X is the big one
        const float* t = X; X = A; A = t;
    }
    float* Y = (float*)d_out;

    cudaFuncSetAttribute(butterfly_kernel,
                         cudaFuncAttributeMaxDynamicSharedMemorySize, 65536);

    sincos_kernel<<<(DEPTH * HALF + 255) / 256, 256>>>(A);
    butterfly_kernel<<<NBLOCKS, NTHREADS, 65536>>>(X, Y);
}

// round 4
// speedup vs baseline: 1.0800x; 1.0800x over previous
#include <cuda_runtime.h>

typedef unsigned long long u64;

#define WIDTH    1024
#define HALF     512
#define BATCH    8192
#define DEPTH    20
#define TB       16          // batch columns per block
#define NTHREADS 256         // 32 row-threads x 8 batch-pair threads
#define NBLOCKS  (BATCH / TB)

// Pre-packed coefficients: { (c,c), (s,s) } as 2x f32x2 (16B).
// P1-type layers (l%10 < 5) are stored PERMUTED: natural pair index p goes to
// slot (p&15)*32 + (p>>4). Then BOTH pass types address coefs as m*32 + rt,
// and a warp's 4 rt values read 4 consecutive 16B entries (64B, one 128B line)
// -> 1 L1 wavefront per coefficient load.
__device__ ulonglong2 g_pk[DEPTH * HALF];

__global__ void sincos_kernel(const float* __restrict__ ang) {
    int i = blockIdx.x * blockDim.x + threadIdx.x;
    if (i < DEPTH * HALF) {
        const int l = i / HALF;
        const int p = i % HALF;
        float s, c;
        sincosf(ang[i], &s, &c);
        u64 cc, ss;
        asm("mov.b64 %0, {%1, %1};" : "=l"(cc) : "f"(c));
        asm("mov.b64 %0, {%1, %1};" : "=l"(ss) : "f"(s));
        const int slot = ((l % 10) < 5) ? ((p & 15) * 32 + (p >> 4)) : p;
        g_pk[l * HALF + slot] = make_ulonglong2(cc, ss);
    }
}

// ---- packed f32x2 helpers (sm_100) ----
__device__ __forceinline__ u64 mul2(u64 a, u64 b) {
    u64 d; asm("mul.rn.f32x2 %0, %1, %2;" : "=l"(d) : "l"(a), "l"(b)); return d;
}
__device__ __forceinline__ u64 fma2(u64 a, u64 b, u64 c) {
    u64 d; asm("fma.rn.f32x2 %0, %1, %2, %3;" : "=l"(d) : "l"(a), "l"(b), "l"(c)); return d;
}

// Givens rotation: y0 = c*x0 + s*x1 ; y1 = -s*x0 + c*x1 (on 2 packed batches)
__device__ __forceinline__ void rot(u64& x0, u64& x1, const ulonglong2 cs) {
    const u64 ns = cs.y ^ 0x8000000080000000ULL;
    const u64 y0 = fma2(cs.x, x0, mul2(cs.y, x1));
    const u64 y1 = fma2(ns,   x0, mul2(cs.x, x1));
    x0 = y0; x1 = y1;
}

// Five butterfly levels fully in registers. With the permuted table, register
// pairing and coefficient addressing are IDENTICAL for both layouts:
//   coef slot = m*32 + rt ; rotation pairs (j, j + 2^l), j = ((m>>l)<<(l+1)) | (m & (2^l - 1))
__device__ __forceinline__ void pass5(u64* Xv, const ulonglong2* __restrict__ lt) {
#pragma unroll
    for (int l = 0; l < 5; ++l) {
#pragma unroll
        for (int q = 0; q < 4; ++q) {
            ulonglong2 cf[4];
#pragma unroll
            for (int t = 0; t < 4; ++t)
                cf[t] = __ldg(lt + l * HALF + (q * 4 + t) * 32);
#pragma unroll
            for (int t = 0; t < 4; ++t) {
                const int m  = q * 4 + t;
                const int sg = 1 << l;
                const int j  = ((m >> l) << (l + 1)) | (m & (sg - 1));
                rot(Xv[j], Xv[j + sg], cf[t]);
            }
        }
    }
}

// Smem swizzle (u64 units): P(row,bp) = (row>>1)*16 + ((bp | ((row&1)<<3)) ^ x4(row>>5)),
// x4(e) = (e&7) | ((e&1)<<3). Enumerated: exactly 2 lanes per 8B bank-pair in BOTH
// warp groupings (rows rt*32+j and rt+32j) -> optimal 2-phase 256B warp accesses.
// The XOR folds into per-thread bases below (1 LOP3 per access).
#define X4J(j) (((j) & 7) | (((j) & 1) << 3))
#define PA(j)  ((baseA ^ (((j) & 1) << 3)) + (((j) >> 1) * 16))   // row = rt*32+j
#define PB(j)  ((baseB ^ X4J(j)) + (j) * 256)                     // row = rt+32j

extern "C" __global__ void __launch_bounds__(NTHREADS, 2)
butterfly_kernel(const float* __restrict__ X, float* __restrict__ Y)
{
    extern __shared__ u64 tile[];          // 8192 u64 = 64 KB

    const int bp = threadIdx.x & 7;        // batch-pair (2 cols) 0..7
    const int rt = threadIdx.x >> 3;       // row-thread 0..31
    const long long bb = (long long)blockIdx.x * TB + bp * 2;

    const int x4rt  = (rt & 7) | ((rt & 1) << 3);
    const int baseA = rt * 256 + (bp ^ x4rt);
    const int baseB = (rt >> 1) * 16 + (bp | ((rt & 1) << 3));

    u64 Xa[32];                            // 32 rows x 2 batch columns

    // Load, layout A: reg j = row rt*32+j
#pragma unroll
    for (int j = 0; j < 32; ++j)
        Xa[j] = *reinterpret_cast<const u64*>(X + (long long)(rt * 32 + j) * BATCH + bb);

    const ulonglong2* lt = g_pk + rt;

#pragma unroll 1
    for (int sp = 0; sp < 2; ++sp) {
        // layers sp*10 .. sp*10+4 (register strides 1..16 in layout A)
        pass5(Xa, lt + (sp * 10) * HALF);

        // exchange A -> B
        __syncthreads();
#pragma unroll
        for (int j = 0; j < 32; ++j) tile[PA(j)] = Xa[j];
        __syncthreads();
#pragma unroll
        for (int j = 0; j < 32; ++j) Xa[j] = tile[PB(j)];

        // layers sp*10+5 .. sp*10+9 (strides 32..512 in layout B)
        pass5(Xa, lt + (sp * 10 + 5) * HALF);

        if (sp == 0) {
            // exchange B -> A
            __syncthreads();
#pragma unroll
            for (int j = 0; j < 32; ++j) tile[PB(j)] = Xa[j];
            __syncthreads();
#pragma unroll
            for (int j = 0; j < 32; ++j) Xa[j] = tile[PA(j)];
        }
    }

    // Store, layout B: reg j = row rt+32j
#pragma unroll
    for (int j = 0; j < 32; ++j)
        *reinterpret_cast<u64*>(Y + (long long)(rt + 32 * j) * BATCH + bb) = Xa[j];
}

extern "C" void kernel_launch(void* const* d_in, const int* in_sizes, int n_in,
                              void* d_out, int out_size)
{
    const float* X = (const float*)d_in[0];
    const float* A = (const float*)d_in[1];
    if (n_in >= 2 && in_sizes[0] < in_sizes[1]) {   // defensive: X is the big one
        const float* t = X; X = A; A = t;
    }
    float* Y = (float*)d_out;

    cudaFuncSetAttribute(butterfly_kernel,
                         cudaFuncAttributeMaxDynamicSharedMemorySize, 65536);

    sincos_kernel<<<(DEPTH * HALF + 255) / 256, 256>>>(A);
    butterfly_kernel<<<NBLOCKS, NTHREADS, 65536>>>(X, Y);
}

// round 5
// speedup vs baseline: 1.1306x; 1.0469x over previous
#include <cuda_runtime.h>

typedef unsigned long long u64;

#define HALF     512
#define BATCH    8192
#define DEPTH    20
#define TB       16          // batch columns per block (4 bp threads x 4 cols)
#define NTHREADS 128         // 32 row-threads x 4 batch-quad threads
#define NBLOCKS  (BATCH / TB)

// Scalar (c, s) coefficients, 8B each. P1-type layers (l%10 < 5) are stored
// PERMUTED: natural pair index p -> slot (p&15)*32 + (p>>4), so BOTH pass
// types address coefs as m*32 + rt and a warp's 8 consecutive rt values read
// 64 consecutive bytes (one line, 2 L1 return cycles for the 256B).
__device__ float2 g_cs[DEPTH * HALF];

__global__ void sincos_kernel(const float* __restrict__ ang) {
    int i = blockIdx.x * blockDim.x + threadIdx.x;
    if (i < DEPTH * HALF) {
        const int l = i / HALF;
        const int p = i % HALF;
        float s, c;
        sincosf(ang[i], &s, &c);
        const int slot = ((l % 10) < 5) ? ((p & 15) * 32 + (p >> 4)) : p;
        g_cs[l * HALF + slot] = make_float2(c, s);
    }
}

// ---- packed f32x2 helpers (sm_100) ----
__device__ __forceinline__ u64 pk2(float v) {
    u64 r; asm("mov.b64 %0, {%1, %1};" : "=l"(r) : "f"(v)); return r;
}
__device__ __forceinline__ u64 mul2(u64 a, u64 b) {
    u64 d; asm("mul.rn.f32x2 %0, %1, %2;" : "=l"(d) : "l"(a), "l"(b)); return d;
}
__device__ __forceinline__ u64 fma2(u64 a, u64 b, u64 c) {
    u64 d; asm("fma.rn.f32x2 %0, %1, %2, %3;" : "=l"(d) : "l"(a), "l"(b), "l"(c)); return d;
}

// Givens rotation on one packed pair: y0 = c*x0 + s*x1 ; y1 = -s*x0 + c*x1
__device__ __forceinline__ void rot(u64& x0, u64& x1, u64 cc, u64 ss, u64 ns) {
    const u64 y0 = fma2(cc, x0, mul2(ss, x1));
    const u64 y1 = fma2(ns, x0, mul2(cc, x1));
    x0 = y0; x1 = y1;
}

// Five butterfly levels fully in registers (4 batch columns: Xa = cols 0-1, Xb = cols 2-3).
// Coef slot = m*32 + rt; rotation pairs (j, j+2^l), j = ((m>>l)<<(l+1)) | (m & (2^l-1)).
__device__ __forceinline__ void pass5(u64* Xa, u64* Xb, const float2* __restrict__ lt) {
#pragma unroll
    for (int l = 0; l < 5; ++l) {
#pragma unroll
        for (int q = 0; q < 4; ++q) {
            float2 cf[4];
#pragma unroll
            for (int t = 0; t < 4; ++t)
                cf[t] = __ldg(lt + l * HALF + (q * 4 + t) * 32);
#pragma unroll
            for (int t = 0; t < 4; ++t) {
                const int m  = q * 4 + t;
                const int sg = 1 << l;
                const int j  = ((m >> l) << (l + 1)) | (m & (sg - 1));
                const u64 cc = pk2(cf[t].x);
                const u64 ss = pk2(cf[t].y);
                const u64 ns = ss ^ 0x8000000080000000ULL;
                rot(Xa[j], Xa[j + sg], cc, ss, ns);
                rot(Xb[j], Xb[j + sg], cc, ss, ns);
            }
        }
    }
}

// Smem swizzle in 16B units: addr(row,bp) = ((row ^ ((row>>5)&1)) << 2) | bp.
// For warp = 8 consecutive rt x 4 bp, in BOTH groupings (rows rt*32+j and
// rows rt+32j) every 128B bank-group is hit by exactly 4 lanes ->
// 512B warp accesses complete in the 4-phase minimum. Bijective.
#define ADRA(j) (baseA + (((j) ^ eA) << 2))                 // row = rt*32+j
#define ADRB(j) ((j) * 128 + (((j) & 1) ? baseB1 : baseB0)) // row = rt+32j

extern "C" __global__ void __launch_bounds__(NTHREADS, 3)
butterfly_kernel(const float* __restrict__ X, float* __restrict__ Y)
{
    extern __shared__ ulonglong2 tile[];   // 1024 rows x 4 bp x 16B = 64 KB

    const int bp = threadIdx.x & 3;        // batch-quad (4 cols) 0..3
    const int rt = threadIdx.x >> 2;       // row-thread 0..31
    const long long bb = (long long)blockIdx.x * TB + bp * 4;

    const int eA     = rt & 1;
    const int baseA  = rt * 128 + bp;
    const int baseB0 = (rt << 2) + bp;
    const int baseB1 = ((rt ^ 1) << 2) + bp;

    u64 Xa[32], Xb[32];                    // 32 rows x 4 batch columns

    // Load, layout A: reg j = row rt*32+j
#pragma unroll
    for (int j = 0; j < 32; ++j) {
        const ulonglong2 v =
            *reinterpret_cast<const ulonglong2*>(X + (long long)(rt * 32 + j) * BATCH + bb);
        Xa[j] = v.x; Xb[j] = v.y;
    }

    const float2* lt = g_cs + rt;

#pragma unroll 1
    for (int sp = 0; sp < 2; ++sp) {
        // layers sp*10 .. sp*10+4 (register strides 1..16 in layout A)
        pass5(Xa, Xb, lt + (sp * 10) * HALF);

        // exchange A -> B
        __syncthreads();
#pragma unroll
        for (int j = 0; j < 32; ++j) tile[ADRA(j)] = make_ulonglong2(Xa[j], Xb[j]);
        __syncthreads();
#pragma unroll
        for (int j = 0; j < 32; ++j) {
            const ulonglong2 v = tile[ADRB(j)];
            Xa[j] = v.x; Xb[j] = v.y;
        }

        // layers sp*10+5 .. sp*10+9 (strides 32..512 in layout B)
        pass5(Xa, Xb, lt + (sp * 10 + 5) * HALF);

        if (sp == 0) {
            // exchange B -> A
            __syncthreads();
#pragma unroll
            for (int j = 0; j < 32; ++j) tile[ADRB(j)] = make_ulonglong2(Xa[j], Xb[j]);
            __syncthreads();
#pragma unroll
            for (int j = 0; j < 32; ++j) {
                const ulonglong2 v = tile[ADRA(j)];
                Xa[j] = v.x; Xb[j] = v.y;
            }
        }
    }

    // Store, layout B: reg j = row rt+32j
#pragma unroll
    for (int j = 0; j < 32; ++j)
        *reinterpret_cast<ulonglong2*>(Y + (long long)(rt + 32 * j) * BATCH + bb) =
            make_ulonglong2(Xa[j], Xb[j]);
}

extern "C" void kernel_launch(void* const* d_in, const int* in_sizes, int n_in,
                              void* d_out, int out_size)
{
    const float* X = (const float*)d_in[0];
    const float* A = (const float*)d_in[1];
    if (n_in >= 2 && in_sizes[0] < in_sizes[1]) {   // defensive: X is the big one
        const float* t = X; X = A; A = t;
    }
    float* Y = (float*)d_out;

    cudaFuncSetAttribute(butterfly_kernel,
                         cudaFuncAttributeMaxDynamicSharedMemorySize, 65536);

    sincos_kernel<<<(DEPTH * HALF + 255) / 256, 256>>>(A);
    butterfly_kernel<<<NBLOCKS, NTHREADS, 65536>>>(X, Y);
}